// round 5
// baseline (speedup 1.0000x reference)
#include <cuda_runtime.h>
#include <cstdint>

// SyntheticTripletLoss closed form: per valid row only
//   pp=<p,p>, tt=<t,t>, pt=<p,t>
//   sim_pn = (pp - pt^2) / max(sqrt(pp - 2pt^2 + pt^2*tt), EPS)
//   loss   = max(MARGIN + sim_pn - pt, 0); mean over valid rows.
//
// R5: stream via cp.async.bulk (TMA-class bulk engine) into smem instead of
// per-lane LDG — the LTS cap is path-independent and the LDG path has been
// pinned at ~2.5 TB/s across occupancy/MLP sweeps. Each block bulk-copies an
// 8-row tile of preds+targets (16KB+16KB), warps reduce rows from smem.

#define MARGIN 0.5f
#define EPS_N 1e-12f

static constexpr int B = 32;
static constexpr int T = 512;
static constexpr int D = 512;
static constexpr int ROW_BYTES = D * 4;                 // 2048
static constexpr int TILE_ROWS = 8;
static constexpr int TILE_BYTES = TILE_ROWS * ROW_BYTES; // 16384
static constexpr int NBLK = (B * T) / TILE_ROWS;         // 2048
static constexpr int THREADS = 256;                      // 8 warps, 1 row each

__device__ float g_partials[NBLK];
__device__ unsigned int g_ticket;   // zero-init; last block resets each run

__device__ __forceinline__ float row_loss(float pp, float tt, float pt) {
    float pt2  = pt * pt;
    float n2   = fmaxf(pp - 2.0f * pt2 + pt2 * tt, 0.0f);
    float norm = fmaxf(sqrtf(n2), EPS_N);
    return fmaxf(MARGIN + (pp - pt2) / norm - pt, 0.0f);
}

__device__ __forceinline__ uint32_t smem_u32(const void* p) {
    return (uint32_t)__cvta_generic_to_shared(p);
}

__global__ __launch_bounds__(THREADS)
void triplet_bulk_kernel(const float* __restrict__ preds,
                         const float* __restrict__ targets,
                         const int* __restrict__ lengths,
                         float* __restrict__ out) {
    __shared__ alignas(128) float4 s_p[TILE_ROWS * (D / 4)];  // 16KB
    __shared__ alignas(128) float4 s_t[TILE_ROWS * (D / 4)];  // 16KB
    __shared__ alignas(8) uint64_t s_mbar;
    __shared__ float s_warp[THREADS / 32];
    __shared__ bool  s_is_last;

    const int warp = threadIdx.x >> 5;
    const int lane = threadIdx.x & 31;
    const int b    = blockIdx.x >> 6;          // 64 tiles per batch row
    const int tile = blockIdx.x & 63;
    const int row0 = blockIdx.x * TILE_ROWS;   // == b*T + tile*TILE_ROWS

    const int len   = __ldg(&lengths[b]);
    const int vrows = min(TILE_ROWS, max(0, len - tile * TILE_ROWS));

    float loss = 0.0f;

    if (vrows > 0) {
        const uint32_t mbar = smem_u32(&s_mbar);
        if (threadIdx.x == 0) {
            asm volatile("mbarrier.init.shared.b64 [%0], 1;"
                         :: "r"(mbar) : "memory");
        }
        __syncthreads();

        const uint32_t vbytes = (uint32_t)vrows * ROW_BYTES;
        if (threadIdx.x == 0) {
            asm volatile("mbarrier.arrive.expect_tx.shared.b64 _, [%0], %1;"
                         :: "r"(mbar), "r"(2u * vbytes) : "memory");
            asm volatile(
                "cp.async.bulk.shared::cta.global.mbarrier::complete_tx::bytes "
                "[%0], [%1], %2, [%3];"
                :: "r"(smem_u32(s_p)),
                   "l"(preds + (size_t)row0 * D),
                   "r"(vbytes), "r"(mbar) : "memory");
            asm volatile(
                "cp.async.bulk.shared::cta.global.mbarrier::complete_tx::bytes "
                "[%0], [%1], %2, [%3];"
                :: "r"(smem_u32(s_t)),
                   "l"(targets + (size_t)row0 * D),
                   "r"(vbytes), "r"(mbar) : "memory");
        }

        // Only warps that will read smem need to wait.
        if (warp < vrows) {
            // acquire-parity wait, phase 0 (barrier freshly init'ed)
            uint32_t done;
            asm volatile(
                "{\n\t.reg .pred p;\n\t"
                "mbarrier.try_wait.parity.acquire.cta.shared::cta.b64 p, [%1], %2;\n\t"
                "selp.b32 %0, 1, 0, p;\n\t}"
                : "=r"(done) : "r"(mbar), "r"(0u) : "memory");
            if (!done) {
                asm volatile(
                    "{\n\t.reg .pred P1;\n\t"
                    "W_%=:\n\t"
                    "mbarrier.try_wait.parity.acquire.cta.shared::cta.b64 P1, [%0], %1, 0x989680;\n\t"
                    "@P1 bra.uni D_%=;\n\t"
                    "bra.uni W_%=;\n\t"
                    "D_%=:\n\t}"
                    :: "r"(mbar), "r"(0u) : "memory");
            }

            const float4* __restrict__ pr = s_p + warp * (D / 4);
            const float4* __restrict__ tr = s_t + warp * (D / 4);
            float4 a0 = pr[lane];      float4 a1 = pr[lane + 32];
            float4 a2 = pr[lane + 64]; float4 a3 = pr[lane + 96];
            float4 c0 = tr[lane];      float4 c1 = tr[lane + 32];
            float4 c2 = tr[lane + 64]; float4 c3 = tr[lane + 96];

            float pp = 0.f, tt = 0.f, pt = 0.f;
            #define ACC(a, c)                                                        \
                pp = fmaf(a.x, a.x, fmaf(a.y, a.y, fmaf(a.z, a.z, fmaf(a.w, a.w, pp)))); \
                tt = fmaf(c.x, c.x, fmaf(c.y, c.y, fmaf(c.z, c.z, fmaf(c.w, c.w, tt)))); \
                pt = fmaf(a.x, c.x, fmaf(a.y, c.y, fmaf(a.z, c.z, fmaf(a.w, c.w, pt))));
            ACC(a0, c0) ACC(a1, c1) ACC(a2, c2) ACC(a3, c3)
            #undef ACC

            #pragma unroll
            for (int off = 16; off; off >>= 1) {
                pp += __shfl_xor_sync(0xffffffffu, pp, off);
                tt += __shfl_xor_sync(0xffffffffu, tt, off);
                pt += __shfl_xor_sync(0xffffffffu, pt, off);
            }
            loss = row_loss(pp, tt, pt);
        }
    }

    // ---- block partial (fixed slot: deterministic) + acq_rel ticket ----
    if (lane == 0) s_warp[warp] = loss;
    __syncthreads();

    if (threadIdx.x == 0) {
        float sum = 0.f;
        #pragma unroll
        for (int i = 0; i < THREADS / 32; i++) sum += s_warp[i];
        g_partials[blockIdx.x] = sum;
        unsigned int old;
        asm volatile("atom.acq_rel.gpu.global.add.u32 %0, [%1], 1;"
                     : "=r"(old) : "l"(&g_ticket) : "memory");
        s_is_last = (old == (unsigned int)(NBLK - 1));
    }
    __syncthreads();
    if (!s_is_last) return;

    // ---- last block: reduce 2048 partials (L2-resident), fixed order ----
    __shared__ float s_red[THREADS];
    float sum = 0.f;
    #pragma unroll
    for (int k = 0; k < NBLK / THREADS; k++)
        sum += __ldcg(&g_partials[threadIdx.x + k * THREADS]);
    s_red[threadIdx.x] = sum;
    __syncthreads();
    #pragma unroll
    for (int off = THREADS / 2; off; off >>= 1) {
        if (threadIdx.x < off) s_red[threadIdx.x] += s_red[threadIdx.x + off];
        __syncthreads();
    }
    if (threadIdx.x == 0) {
        int cnt = 0;
        #pragma unroll
        for (int i = 0; i < B; i++) cnt += __ldg(&lengths[i]);
        out[0] = s_red[0] / (float)cnt;
        g_ticket = 0;   // reset for next graph replay
    }
}

extern "C" void kernel_launch(void* const* d_in, const int* in_sizes, int n_in,
                              void* d_out, int out_size) {
    const float* preds   = (const float*)d_in[0];
    const float* targets = (const float*)d_in[1];
    const int*   lengths = (const int*)d_in[2];
    float* out = (float*)d_out;

    triplet_bulk_kernel<<<NBLK, THREADS>>>(preds, targets, lengths, out);
}

// round 7
// speedup vs baseline: 1.1221x; 1.1221x over previous
#include <cuda_runtime.h>
#include <cstdint>

// SyntheticTripletLoss closed form: per valid row only
//   pp=<p,p>, tt=<t,t>, pt=<p,t>
//   sim_pn = (pp - pt^2) / max(sqrt(pp - 2pt^2 + pt^2*tt), EPS)
//   loss   = max(MARGIN + sim_pn - pt, 0); mean over valid rows.
//
// R7 = R6 with compile fix: 256-bit LDG (.v8.b32, required for
// L2::evict_last) for targets; preds via cp.async.bulk with evict_last
// cache hint. Dual queues + 256b entries + L2 residency across replays.

#define MARGIN 0.5f
#define EPS_N 1e-12f

static constexpr int B = 32;
static constexpr int T = 512;
static constexpr int D = 512;
static constexpr int ROW_BYTES = D * 4;                  // 2048
static constexpr int TILE_ROWS = 8;
static constexpr int NBLK = (B * T) / TILE_ROWS;         // 2048
static constexpr int THREADS = 256;                      // 8 warps, 1 row each

__device__ float g_partials[NBLK];
__device__ unsigned int g_ticket;   // zero-init; last block resets each run

__device__ __forceinline__ float row_loss(float pp, float tt, float pt) {
    float pt2  = pt * pt;
    float n2   = fmaxf(pp - 2.0f * pt2 + pt2 * tt, 0.0f);
    float norm = fmaxf(sqrtf(n2), EPS_N);
    return fmaxf(MARGIN + (pp - pt2) / norm - pt, 0.0f);
}

__device__ __forceinline__ uint32_t smem_u32(const void* p) {
    return (uint32_t)__cvta_generic_to_shared(p);
}

// 256-bit non-coherent global load with L2 evict_last.
__device__ __forceinline__ void ldg256_el(const float* p, float* v) {
    uint32_t r0, r1, r2, r3, r4, r5, r6, r7;
    asm volatile(
        "ld.global.nc.L2::evict_last.v8.b32 {%0,%1,%2,%3,%4,%5,%6,%7}, [%8];"
        : "=r"(r0), "=r"(r1), "=r"(r2), "=r"(r3),
          "=r"(r4), "=r"(r5), "=r"(r6), "=r"(r7)
        : "l"(p));
    v[0] = __uint_as_float(r0); v[1] = __uint_as_float(r1);
    v[2] = __uint_as_float(r2); v[3] = __uint_as_float(r3);
    v[4] = __uint_as_float(r4); v[5] = __uint_as_float(r5);
    v[6] = __uint_as_float(r6); v[7] = __uint_as_float(r7);
}

__global__ __launch_bounds__(THREADS)
void triplet_dual_kernel(const float* __restrict__ preds,
                         const float* __restrict__ targets,
                         const int* __restrict__ lengths,
                         float* __restrict__ out) {
    __shared__ alignas(128) float4 s_p[TILE_ROWS * (D / 4)];  // 16KB preds tile
    __shared__ alignas(8) uint64_t s_mbar;
    __shared__ float s_warp[THREADS / 32];
    __shared__ bool  s_is_last;

    const int warp = threadIdx.x >> 5;
    const int lane = threadIdx.x & 31;
    const int b    = blockIdx.x >> 6;          // 64 tiles per batch row
    const int tile = blockIdx.x & 63;
    const int row0 = blockIdx.x * TILE_ROWS;   // == b*T + tile*TILE_ROWS

    const int len    = __ldg(&lengths[b]);
    const int vrows  = min(TILE_ROWS, max(0, len - tile * TILE_ROWS));
    const bool active = (warp < vrows);

    // ---- targets: two 256-bit LDGs per lane, issued FIRST (fills the LSU
    //      queue while the bulk engine independently pulls preds) ----
    float c[16];
    if (active) {
        const float* __restrict__ t4 = targets + (size_t)(row0 + warp) * D;
        ldg256_el(t4 + lane * 8, c);             // floats [0,256)
        ldg256_el(t4 + 256 + lane * 8, c + 8);   // floats [256,512)
    }

    float loss = 0.0f;

    if (vrows > 0) {
        const uint32_t mbar = smem_u32(&s_mbar);
        if (threadIdx.x == 0) {
            asm volatile("mbarrier.init.shared.b64 [%0], 1;"
                         :: "r"(mbar) : "memory");
        }
        __syncthreads();

        const uint32_t vbytes = (uint32_t)vrows * ROW_BYTES;
        if (threadIdx.x == 0) {
            uint64_t pol;
            asm volatile("createpolicy.fractional.L2::evict_last.b64 %0, 1.0;"
                         : "=l"(pol));
            asm volatile("mbarrier.arrive.expect_tx.shared.b64 _, [%0], %1;"
                         :: "r"(mbar), "r"(vbytes) : "memory");
            asm volatile(
                "cp.async.bulk.shared::cta.global.mbarrier::complete_tx::bytes"
                ".L2::cache_hint [%0], [%1], %2, [%3], %4;"
                :: "r"(smem_u32(s_p)),
                   "l"(preds + (size_t)row0 * D),
                   "r"(vbytes), "r"(mbar), "l"(pol) : "memory");
        }

        if (active) {
            // acquire-parity wait, phase 0 (single-use barrier)
            uint32_t done;
            asm volatile(
                "{\n\t.reg .pred p;\n\t"
                "mbarrier.try_wait.parity.acquire.cta.shared::cta.b64 p, [%1], %2;\n\t"
                "selp.b32 %0, 1, 0, p;\n\t}"
                : "=r"(done) : "r"(mbar), "r"(0u) : "memory");
            if (!done) {
                asm volatile(
                    "{\n\t.reg .pred P1;\n\t"
                    "W_%=:\n\t"
                    "mbarrier.try_wait.parity.acquire.cta.shared::cta.b64 P1, [%0], %1, 0x989680;\n\t"
                    "@P1 bra.uni D_%=;\n\t"
                    "bra.uni W_%=;\n\t"
                    "D_%=:\n\t}"
                    :: "r"(mbar), "r"(0u) : "memory");
            }

            // preds row from smem: same float layout as the LDG side
            // (lane*8 .. lane*8+7 and +256), conflict-free 128-bit LDS.
            const float4* __restrict__ pr = s_p + warp * (D / 4);
            float4 a0 = pr[lane * 2];
            float4 a1 = pr[lane * 2 + 1];
            float4 a2 = pr[64 + lane * 2];
            float4 a3 = pr[64 + lane * 2 + 1];
            const float a[16] = { a0.x, a0.y, a0.z, a0.w,
                                  a1.x, a1.y, a1.z, a1.w,
                                  a2.x, a2.y, a2.z, a2.w,
                                  a3.x, a3.y, a3.z, a3.w };

            float pp = 0.f, tt = 0.f, pt = 0.f;
            #pragma unroll
            for (int i = 0; i < 16; i++) {
                pp = fmaf(a[i], a[i], pp);
                tt = fmaf(c[i], c[i], tt);
                pt = fmaf(a[i], c[i], pt);
            }

            #pragma unroll
            for (int off = 16; off; off >>= 1) {
                pp += __shfl_xor_sync(0xffffffffu, pp, off);
                tt += __shfl_xor_sync(0xffffffffu, tt, off);
                pt += __shfl_xor_sync(0xffffffffu, pt, off);
            }
            loss = row_loss(pp, tt, pt);
        }
    }

    // ---- block partial (fixed slot: deterministic) + acq_rel ticket ----
    if (lane == 0) s_warp[warp] = loss;
    __syncthreads();

    if (threadIdx.x == 0) {
        float sum = 0.f;
        #pragma unroll
        for (int i = 0; i < THREADS / 32; i++) sum += s_warp[i];
        g_partials[blockIdx.x] = sum;
        unsigned int old;
        asm volatile("atom.acq_rel.gpu.global.add.u32 %0, [%1], 1;"
                     : "=r"(old) : "l"(&g_ticket) : "memory");
        s_is_last = (old == (unsigned int)(NBLK - 1));
    }
    __syncthreads();
    if (!s_is_last) return;

    // ---- last block: reduce 2048 partials (L2-resident), fixed order ----
    __shared__ float s_red[THREADS];
    float sum = 0.f;
    #pragma unroll
    for (int k = 0; k < NBLK / THREADS; k++)
        sum += __ldcg(&g_partials[threadIdx.x + k * THREADS]);
    s_red[threadIdx.x] = sum;
    __syncthreads();
    #pragma unroll
    for (int off = THREADS / 2; off; off >>= 1) {
        if (threadIdx.x < off) s_red[threadIdx.x] += s_red[threadIdx.x + off];
        __syncthreads();
    }
    if (threadIdx.x == 0) {
        int cnt = 0;
        #pragma unroll
        for (int i = 0; i < B; i++) cnt += __ldg(&lengths[i]);
        out[0] = s_red[0] / (float)cnt;
        g_ticket = 0;   // reset for next graph replay
    }
}

extern "C" void kernel_launch(void* const* d_in, const int* in_sizes, int n_in,
                              void* d_out, int out_size) {
    const float* preds   = (const float*)d_in[0];
    const float* targets = (const float*)d_in[1];
    const int*   lengths = (const int*)d_in[2];
    float* out = (float*)d_out;

    triplet_dual_kernel<<<NBLK, THREADS>>>(preds, targets, lengths, out);
}

// round 8
// speedup vs baseline: 1.1522x; 1.0269x over previous
#include <cuda_runtime.h>

// SyntheticTripletLoss closed form: per valid row only
//   pp=<p,p>, tt=<t,t>, pt=<p,t>
//   sim_pn = (pp - pt^2) / max(sqrt(pp - 2pt^2 + pt^2*tt), EPS)
//   loss   = max(MARGIN + sim_pn - pt, 0); mean over valid rows.
//
// R8: decisive minimal fusion. EXACT R1 streaming body (one row per warp,
// 8 front-batched LDG.128, shuffle reduce — the config whose implied rate
// was ~7 TB/s) + the cheapest possible tail: acq_rel ticket (NO threadfence,
// no CCTL.IVALL) and a last-block fixed-order reduce.

#define MARGIN 0.5f
#define EPS_N 1e-12f

static constexpr int B = 32;
static constexpr int T = 512;
static constexpr int D = 512;
static constexpr int WARPS_PER_BLOCK = 8;
static constexpr int THREADS = WARPS_PER_BLOCK * 32;    // 256
static constexpr int ROWS = B * T;                      // 16384
static constexpr int NBLOCKS = ROWS / WARPS_PER_BLOCK;  // 2048

__device__ float g_partials[NBLOCKS];
__device__ unsigned int g_ticket;   // zero-init; last block resets each run

__global__ __launch_bounds__(THREADS)
void triplet_min_kernel(const float* __restrict__ preds,
                        const float* __restrict__ targets,
                        const int* __restrict__ lengths,
                        float* __restrict__ out) {
    const int warp = threadIdx.x >> 5;
    const int lane = threadIdx.x & 31;
    const int row  = blockIdx.x * WARPS_PER_BLOCK + warp;
    const int b    = row >> 9;        // row / T
    const int t    = row & (T - 1);   // row % T

    float loss = 0.0f;

    if (t < __ldg(&lengths[b])) {
        const float4* __restrict__ p4 =
            reinterpret_cast<const float4*>(preds + (size_t)row * D);
        const float4* __restrict__ t4 =
            reinterpret_cast<const float4*>(targets + (size_t)row * D);

        // 512 floats / 32 lanes = 4 float4 per lane per tensor; front-batch
        // all 8 loads for MLP.
        float4 a0 = __ldg(p4 + lane);
        float4 a1 = __ldg(p4 + lane + 32);
        float4 a2 = __ldg(p4 + lane + 64);
        float4 a3 = __ldg(p4 + lane + 96);
        float4 c0 = __ldg(t4 + lane);
        float4 c1 = __ldg(t4 + lane + 32);
        float4 c2 = __ldg(t4 + lane + 64);
        float4 c3 = __ldg(t4 + lane + 96);

        float pp = 0.f, tt = 0.f, pt = 0.f;
        #define ACC(a, c)                                                        \
            pp = fmaf(a.x, a.x, fmaf(a.y, a.y, fmaf(a.z, a.z, fmaf(a.w, a.w, pp)))); \
            tt = fmaf(c.x, c.x, fmaf(c.y, c.y, fmaf(c.z, c.z, fmaf(c.w, c.w, tt)))); \
            pt = fmaf(a.x, c.x, fmaf(a.y, c.y, fmaf(a.z, c.z, fmaf(a.w, c.w, pt))));
        ACC(a0, c0) ACC(a1, c1) ACC(a2, c2) ACC(a3, c3)
        #undef ACC

        #pragma unroll
        for (int off = 16; off; off >>= 1) {
            pp += __shfl_xor_sync(0xffffffffu, pp, off);
            tt += __shfl_xor_sync(0xffffffffu, tt, off);
            pt += __shfl_xor_sync(0xffffffffu, pt, off);
        }

        float pt2  = pt * pt;
        float n2   = fmaxf(pp - 2.0f * pt2 + pt2 * tt, 0.0f);
        float norm = fmaxf(sqrtf(n2), EPS_N);
        loss = fmaxf(MARGIN + (pp - pt2) / norm - pt, 0.0f);
    }

    __shared__ float s_warp[WARPS_PER_BLOCK];
    __shared__ bool  s_is_last;
    if (lane == 0) s_warp[warp] = loss;
    __syncthreads();

    if (threadIdx.x == 0) {
        float sum = 0.f;
        #pragma unroll
        for (int i = 0; i < WARPS_PER_BLOCK; i++) sum += s_warp[i];
        g_partials[blockIdx.x] = sum;   // fixed slot: deterministic
        // Release-ordered ticket: orders the partial store without a
        // gpu-scope MEMBAR (which would CCTL.IVALL-flush L1D — the R2 bug).
        unsigned int old;
        asm volatile("atom.acq_rel.gpu.global.add.u32 %0, [%1], 1;"
                     : "=r"(old) : "l"(&g_ticket) : "memory");
        s_is_last = (old == (unsigned int)(NBLOCKS - 1));
    }
    __syncthreads();
    if (!s_is_last) return;

    // Last block: reduce 2048 partials (L2-resident) in fixed order.
    __shared__ float s_red[THREADS];
    float sum = 0.f;
    #pragma unroll
    for (int k = 0; k < NBLOCKS / THREADS; k++)
        sum += __ldcg(&g_partials[threadIdx.x + k * THREADS]);
    s_red[threadIdx.x] = sum;
    __syncthreads();
    #pragma unroll
    for (int off = THREADS / 2; off; off >>= 1) {
        if (threadIdx.x < off) s_red[threadIdx.x] += s_red[threadIdx.x + off];
        __syncthreads();
    }
    if (threadIdx.x == 0) {
        int cnt = 0;
        #pragma unroll
        for (int i = 0; i < B; i++) cnt += __ldg(&lengths[i]);
        out[0] = s_red[0] / (float)cnt;
        g_ticket = 0;   // reset for next graph replay
    }
}

extern "C" void kernel_launch(void* const* d_in, const int* in_sizes, int n_in,
                              void* d_out, int out_size) {
    const float* preds   = (const float*)d_in[0];
    const float* targets = (const float*)d_in[1];
    const int*   lengths = (const int*)d_in[2];
    float* out = (float*)d_out;

    triplet_min_kernel<<<NBLOCKS, THREADS>>>(preds, targets, lengths, out);
}